// round 14
// baseline (speedup 1.0000x reference)
#include <cuda_runtime.h>
#include <cuda_bf16.h>
#include <cstdint>

#define OUT_F  4096
#define IN_F   4096
#define NFREQ  10000
#define ROWS   1024
#define SCALE  2.34375f      // 150 / sqrt(4096)

// ---- GEMM tile config (bf16, 128x256, 512 threads, cp.async x3) ----
#define BM 128
#define BN 256
#define BK 32                        // bf16 elems per stage
#define KSTAGES (IN_F / BK)          // 128
#define SROWB 40                     // padded smem row in bf16 (80 B): conflict-free ldmatrix
#define XB_BYTES (BM * SROWB * 2)    // 10240 B
#define WB_BYTES (BN * SROWB * 2)    // 20480 B
#define BUFB (XB_BYTES + WB_BYTES)   // 30720 B per stage
#define NSTAGE 3
#define GEMM_SMEM (NSTAGE * BUFB)    // 92160 B

#define WQ ((size_t)OUT_F * IN_F / 4)   // float4 count of W
#define CVT_BLOCKS 2048                 // 2048 float4 per block

// Scratch (static __device__ — no allocation allowed)
static __device__ float          g_y[(size_t)ROWS * OUT_F];     // 16 MB
static __device__ int            g_last[(size_t)OUT_F * IN_F];  // 64 MB hash (10k slots touched)
static __device__ __nv_bfloat16  g_wb[(size_t)OUT_F * IN_F];    // 32 MB  W in bf16
static __device__ __nv_bfloat16  g_xb[(size_t)ROWS * IN_F];     // 8 MB   X in bf16
static __device__ unsigned       g_pk[NFREQ];                   // (o<<16)|i
static __device__ float          g_sv[NFREQ];                   // valid ? spec : 0

// ======================== PTX helpers ======================================
static __device__ __forceinline__ uint32_t smem_u32(const void* p) {
    uint32_t a;
    asm("{ .reg .u64 t; cvta.to.shared.u64 t, %1; cvt.u32.u64 %0, t; }" : "=r"(a) : "l"(p));
    return a;
}

#define CP_ASYNC16(saddr, gptr) \
    asm volatile("cp.async.cg.shared.global [%0], [%1], 16;" \
                 :: "r"(saddr), "l"(gptr) : "memory")
#define CP_COMMIT() asm volatile("cp.async.commit_group;" ::: "memory")
#define CP_WAIT2()  asm volatile("cp.async.wait_group 2;" ::: "memory")

#define LDSM_X4(r, addr) \
    asm volatile("ldmatrix.sync.aligned.m8n8.x4.shared.b16 {%0,%1,%2,%3}, [%4];" \
                 : "=r"((r)[0]), "=r"((r)[1]), "=r"((r)[2]), "=r"((r)[3]) : "r"(addr))

#define MMA_BF16(c, a, b0, b1) \
    asm volatile("mma.sync.aligned.m16n8k16.row.col.f32.bf16.bf16.f32 " \
                 "{%0,%1,%2,%3}, {%4,%5,%6,%7}, {%8,%9}, {%0,%1,%2,%3};" \
                 : "+f"((c)[0]), "+f"((c)[1]), "+f"((c)[2]), "+f"((c)[3]) \
                 : "r"((a)[0]), "r"((a)[1]), "r"((a)[2]), "r"((a)[3]), \
                   "r"(b0), "r"(b1))

// ======================== fused setup (single CTA) ==========================
__global__ __launch_bounds__(1024)
void k_prep(const void* __restrict__ idxv, const float* __restrict__ spec) {
    __shared__ int s_is32;
    __shared__ unsigned s_pk[NFREQ];   // 40 KB
    const int tid = threadIdx.x;

    if (tid == 0) s_is32 = 0;
    __syncthreads();

    const long long* p64 = (const long long*)idxv;
    for (int k = tid; k < NFREQ; k += 1024)
        if ((unsigned long long)p64[k] >= (unsigned long long)OUT_F) s_is32 = 1;
    __syncthreads();
    const bool is32 = (s_is32 != 0);

    for (int k = tid; k < NFREQ; k += 1024) {
        int o, i;
        if (is32) {
            const int* p = (const int*)idxv;
            o = p[k];           i = p[NFREQ + k];
        } else {
            o = (int)p64[k];    i = (int)p64[NFREQ + k];
        }
        o &= (OUT_F - 1);  i &= (IN_F - 1);
        s_pk[k] = ((unsigned)o << 16) | (unsigned)i;
        g_last[(unsigned)o * (unsigned)IN_F + (unsigned)i] = 0;
    }
    __syncthreads();

    for (int k = tid; k < NFREQ; k += 1024) {
        unsigned pk = s_pk[k];
        atomicMax(&g_last[(pk >> 16) * (unsigned)IN_F + (pk & 0xFFFF)], k + 1);
    }
    __syncthreads();

    for (int k = tid; k < NFREQ; k += 1024) {
        unsigned pk = s_pk[k];
        bool valid = (g_last[(pk >> 16) * (unsigned)IN_F + (pk & 0xFFFF)] == k + 1);
        g_pk[k] = pk;
        g_sv[k] = valid ? spec[k] : 0.0f;
    }
}

// ===== fused pre-pass: blocks [0,ROWS) = scatter+WHT+X->bf16; rest = W->bf16 =====
__global__ __launch_bounds__(512)
void k_pre(const float* __restrict__ x, const float* __restrict__ w) {
    __shared__ __align__(16) float xrow[IN_F];
    __shared__ __align__(16) float yrow[OUT_F];
    const int tid = threadIdx.x;

    if (blockIdx.x >= ROWS) {
        // ---- W -> bf16 slice ----
        size_t base = (size_t)(blockIdx.x - ROWS) * 2048;
        __nv_bfloat162* d = reinterpret_cast<__nv_bfloat162*>(g_wb);
        #pragma unroll
        for (int t = 0; t < 4; ++t) {
            size_t q = base + t * 512 + tid;
            float4 v = reinterpret_cast<const float4*>(w)[q];
            d[2 * q]     = __floats2bfloat162_rn(v.x, v.y);
            d[2 * q + 1] = __floats2bfloat162_rn(v.z, v.w);
        }
        return;
    }

    const int r = blockIdx.x;
    const float4* xg = reinterpret_cast<const float4*>(x + (size_t)r * IN_F);
    for (int j = tid; j < IN_F / 4; j += 512)
        reinterpret_cast<float4*>(xrow)[j] = xg[j];
    for (int j = tid; j < OUT_F / 4; j += 512)
        reinterpret_cast<float4*>(yrow)[j] = make_float4(0.f, 0.f, 0.f, 0.f);
    __syncthreads();

    {   // X -> bf16 (row already in smem)
        __nv_bfloat162* xb = reinterpret_cast<__nv_bfloat162*>(g_xb + (size_t)r * IN_F);
        for (int j = tid; j < IN_F / 2; j += 512)
            xb[j] = __floats2bfloat162_rn(xrow[2 * j], xrow[2 * j + 1]);
    }

    for (int k = tid; k < NFREQ; k += 512) {
        unsigned pk = g_pk[k];
        float s = g_sv[k];
        atomicAdd(&yrow[pk >> 16], xrow[pk & 0xFFFF] * s);
    }
    __syncthreads();

    for (int len = 1; len < OUT_F; len <<= 1) {
        for (int p = tid; p < OUT_F / 2; p += 512) {
            int i0 = 2 * p - (p & (len - 1));
            int i1 = i0 + len;
            float a = yrow[i0], b = yrow[i1];
            yrow[i0] = a + b;
            yrow[i1] = a - b;
        }
        __syncthreads();
    }

    float* yo = g_y + (size_t)r * OUT_F;
    for (int j = tid; j < OUT_F; j += 512) yo[j] = yrow[j] * SCALE;
}

// ======================== bf16 mma.sync GEMM (128x256, 512 thr) =============
// out[r,o] = (X · W^T)[r,o] + g_y[r,o]
// 16 warps (2M x 8N), warp tile 64x32, m16n8k16, cp.async 3-stage, single wave.
__global__ __launch_bounds__(512, 1)
void k_gemm_bf16(float* __restrict__ out) {
    extern __shared__ __align__(16) char smem[];
    const uint32_t sb = smem_u32(smem);

    const int tid  = threadIdx.x;
    const int wid  = tid >> 5;
    const int lane = tid & 31;
    const int warpM = wid >> 3;          // 0..1  (64 rows)
    const int warpN = wid & 7;           // 0..7  (32 cols)
    const int bn = blockIdx.x;           // 0..15
    const int bm = blockIdx.y;           // 0..7

    const __nv_bfloat16* xg = g_xb + (size_t)bm * BM * IN_F;
    const __nv_bfloat16* wg = g_wb + (size_t)bn * BN * IN_F;

    // Loader mapping: X = 512 x 16B (1/thread), W = 1024 x 16B (2/thread).
    const int xr = tid >> 2, xc = tid & 3;
    const uint32_t xsb = (uint32_t)(xr * (SROWB * 2) + xc * 16);
    int wr[2]; uint32_t wsb[2]; int wc[2];
    #pragma unroll
    for (int t = 0; t < 2; ++t) {
        int f = tid + t * 512;
        wr[t] = f >> 2;  wc[t] = f & 3;
        wsb[t] = (uint32_t)(wr[t] * (SROWB * 2) + wc[t] * 16);
    }

    // ldmatrix per-lane byte offsets within an operand buffer.
    uint32_t aoff[4];
    #pragma unroll
    for (int mt = 0; mt < 4; ++mt) {
        int rr = warpM * 64 + mt * 16 + (lane & 15);
        aoff[mt] = (uint32_t)(rr * (SROWB * 2) + (lane >> 4) * 16);
    }
    uint32_t boff[2];
    #pragma unroll
    for (int p = 0; p < 2; ++p) {
        int rr = warpN * 32 + p * 16 + (lane & 7) + ((lane >> 4) & 1) * 8;
        boff[p] = (uint32_t)(rr * (SROWB * 2) + ((lane >> 3) & 1) * 16);
    }

    float acc[4][4][4];
    #pragma unroll
    for (int mt = 0; mt < 4; ++mt)
        #pragma unroll
        for (int nt = 0; nt < 4; ++nt)
            #pragma unroll
            for (int j = 0; j < 4; ++j) acc[mt][nt][j] = 0.f;

    // Prologue: issue stages 0 and 1.
    #pragma unroll
    for (int s = 0; s < 2; ++s) {
        const uint32_t xb = sb + s * BUFB;
        const int kk = s * BK;
        CP_ASYNC16(xb + xsb, xg + (size_t)xr * IN_F + kk + xc * 8);
        #pragma unroll
        for (int t = 0; t < 2; ++t)
            CP_ASYNC16(xb + XB_BYTES + wsb[t], wg + (size_t)wr[t] * IN_F + kk + wc[t] * 8);
        CP_COMMIT();
    }

    int buf = 0;
    for (int s = 0; s < KSTAGES; ++s) {
        // issue stage s+2 (overwrites buffer of stage s-1; safe: sync at loop end)
        if (s + 2 < KSTAGES) {
            const int nb = (s + 2) % NSTAGE;
            const uint32_t xb = sb + nb * BUFB;
            const int kk = (s + 2) * BK;
            CP_ASYNC16(xb + xsb, xg + (size_t)xr * IN_F + kk + xc * 8);
            #pragma unroll
            for (int t = 0; t < 2; ++t)
                CP_ASYNC16(xb + XB_BYTES + wsb[t], wg + (size_t)wr[t] * IN_F + kk + wc[t] * 8);
        }
        CP_COMMIT();
        CP_WAIT2();                 // stage s resident
        __syncthreads();

        const uint32_t xsu = sb + buf * BUFB;
        const uint32_t wsu = xsu + XB_BYTES;
        #pragma unroll
        for (int ks = 0; ks < 2; ++ks) {
            uint32_t a[4][4], bq[2][4];
            #pragma unroll
            for (int mt = 0; mt < 4; ++mt) LDSM_X4(a[mt], xsu + aoff[mt] + ks * 32);
            #pragma unroll
            for (int p = 0; p < 2; ++p)  LDSM_X4(bq[p], wsu + boff[p] + ks * 32);
            #pragma unroll
            for (int mt = 0; mt < 4; ++mt) {
                MMA_BF16(acc[mt][0], a[mt], bq[0][0], bq[0][1]);
                MMA_BF16(acc[mt][1], a[mt], bq[0][2], bq[0][3]);
                MMA_BF16(acc[mt][2], a[mt], bq[1][0], bq[1][1]);
                MMA_BF16(acc[mt][3], a[mt], bq[1][2], bq[1][3]);
            }
        }
        __syncthreads();
        buf = (buf + 1 == NSTAGE) ? 0 : buf + 1;
    }

    // Epilogue: c0,c1 at (row, 2*tid4), c2,c3 at (row+8); fuse +g_y.
    const int gid  = lane >> 2;
    const int tid4 = lane & 3;
    #pragma unroll
    for (int mt = 0; mt < 4; ++mt) {
        const int r0 = bm * BM + warpM * 64 + mt * 16 + gid;
        #pragma unroll
        for (int nt = 0; nt < 4; ++nt) {
            const int c = bn * BN + warpN * 32 + nt * 8 + tid4 * 2;
            size_t i0 = (size_t)r0 * OUT_F + c;
            size_t i1 = (size_t)(r0 + 8) * OUT_F + c;
            float2 y0 = *reinterpret_cast<const float2*>(&g_y[i0]);
            float2 y1 = *reinterpret_cast<const float2*>(&g_y[i1]);
            float2 o0 = make_float2(acc[mt][nt][0] + y0.x, acc[mt][nt][1] + y0.y);
            float2 o1 = make_float2(acc[mt][nt][2] + y1.x, acc[mt][nt][3] + y1.y);
            *reinterpret_cast<float2*>(&out[i0]) = o0;
            *reinterpret_cast<float2*>(&out[i1]) = o1;
        }
    }
}

// ---------------------------------------------------------------------------
extern "C" void kernel_launch(void* const* d_in, const int* in_sizes, int n_in,
                              void* d_out, int out_size) {
    const float* x    = (const float*)d_in[0];   // [2,512,4096]
    const float* w    = (const float*)d_in[1];   // [4096,4096]
    const float* spec = (const float*)d_in[2];   // [10000]
    const void*  idx  = d_in[3];                 // [2,10000] int32 or int64
    float* out = (float*)d_out;                  // [2,512,4096]
    (void)in_sizes; (void)n_in; (void)out_size;

    cudaFuncSetAttribute(k_gemm_bf16, cudaFuncAttributeMaxDynamicSharedMemorySize, GEMM_SMEM);

    k_prep     <<<1, 1024>>>(idx, spec);
    k_pre      <<<ROWS + CVT_BLOCKS, 512>>>(x, w);
    k_gemm_bf16<<<dim3(OUT_F / BN, ROWS / BM), 512, GEMM_SMEM>>>(out);
}